// round 8
// baseline (speedup 1.0000x reference)
#include <cuda_runtime.h>
#include <math.h>
#include <stdint.h>

#define N_ROWS 16384
#define DIM 256
#define DT_F 0.01f

// scratch for xi (clipped), passed from MLP kernel to scan kernel
__device__ float g_xi[N_ROWS];

typedef unsigned long long u64;

#define FMA2(acc, a2, b2) \
    asm("fma.rn.f32x2 %0, %1, %2, %3;" : "=l"(acc) : "l"(a2), "l"(b2), "l"(acc))

__device__ __forceinline__ u64 dup2(float a) {
    u64 r; uint32_t au = __float_as_uint(a);
    asm("mov.b64 %0, {%1, %1};" : "=l"(r) : "r"(au));
    return r;
}
__device__ __forceinline__ void unpk(u64 x, float& lo, float& hi) {
    uint32_t l, h;
    asm("mov.b64 {%0, %1}, %2;" : "=r"(l), "=r"(h) : "l"(x));
    lo = __uint_as_float(l); hi = __uint_as_float(h);
}

// ---------------------------------------------------------------------------
// Fused MLP kernel: 128 rows per block, 256 threads (8 warps x 16 rows each),
// packed f32x2 FFMA, 8 column-pairs per thread, double-buffered W tiles.
// ---------------------------------------------------------------------------
#define ROWS 128
#define BK   16
#define RPW  16     // rows per warp (= rows per thread)
// smem floats: Hs 128x256, Xs 128x16, Ws 2 x 16x256
#define OFF_XS (ROWS * DIM)
#define OFF_WS (OFF_XS + ROWS * BK)
#define MLP_SMEM ((ROWS * DIM + ROWS * BK + 2 * BK * DIM) * 4)

extern __shared__ float smem[];

__global__ __launch_bounds__(256, 1)
void mlp_kernel(const float* __restrict__ data,
                const float* __restrict__ omega,
                const float* __restrict__ eps,
                const float* __restrict__ W1,  const float* __restrict__ b1,
                const float* __restrict__ W2,  const float* __restrict__ b2,
                const float* __restrict__ Wm1, const float* __restrict__ bm1,
                const float* __restrict__ Wm2, const float* __restrict__ bm2,
                const float* __restrict__ Wl1, const float* __restrict__ bl1,
                const float* __restrict__ Wl2, const float* __restrict__ bl2,
                float* __restrict__ out)
{
    float* Hs = smem;                        // 128 x 256
    float* Xs = smem + OFF_XS;               // 128 x 16
    float* Ws = smem + OFF_WS;               // 2 x (16 x 256)

    const int tid = threadIdx.x;
    const int tc  = tid & 31;                // lane -> column pairs tc*2 + 64p
    const int wd  = tid >> 5;                // warp id -> rows wd*16 .. +15
    const int row0 = blockIdx.x * ROWS;

    // W-tile prefetch: BK x 256 floats = 1024 float4; 256 threads x 4
    const int pf_k[4] = { tid >> 6, (tid + 256) >> 6, (tid + 512) >> 6, (tid + 768) >> 6 };
    const int pf_c = (tid & 63) * 4;
    // X-tile prefetch: 128 x 16 = 512 float4; 256 threads x 2
    const int px_r0 = tid >> 1,  px_q0 = (tid & 1) * 8;   // two float4 = 8 floats

    u64 acc[RPW][4];
    float4 wreg[4];

    // =======================================================================
    // Stage 1: Hs = relu([data|omega] @ W1 + b1)
    // =======================================================================
    #pragma unroll
    for (int i = 0; i < RPW; i++)
        #pragma unroll
        for (int p = 0; p < 4; p++) acc[i][p] = 0ull;

    // load X (whole 128x16 per tile handled per-iteration below); W prolog:
    #pragma unroll
    for (int u = 0; u < 4; u++)
        wreg[u] = *(const float4*)&W1[(size_t)pf_k[u] * DIM + pf_c];
    #pragma unroll
    for (int u = 0; u < 4; u++)
        *(float4*)&Ws[pf_k[u] * DIM + pf_c] = wreg[u];
    #pragma unroll
    for (int u = 0; u < 4; u++)
        wreg[u] = *(const float4*)&W1[(size_t)(BK + pf_k[u]) * DIM + pf_c];
    // X tile 0
    {
        float4 x0 = *(const float4*)&data[(size_t)(row0 + px_r0) * DIM + px_q0];
        float4 x1 = *(const float4*)&data[(size_t)(row0 + px_r0) * DIM + px_q0 + 4];
        *(float4*)&Xs[px_r0 * BK + px_q0]     = x0;
        *(float4*)&Xs[px_r0 * BK + px_q0 + 4] = x1;
    }

    for (int t = 0; t < 16; t++) {
        const int buf = t & 1;
        if (t > 0) {
            #pragma unroll
            for (int u = 0; u < 4; u++)
                *(float4*)&Ws[buf * BK * DIM + pf_k[u] * DIM + pf_c] = wreg[u];
        }
        __syncthreads();
        if (t + 1 < 16) {
            #pragma unroll
            for (int u = 0; u < 4; u++)
                wreg[u] = *(const float4*)&W1[(size_t)((t + 1) * BK + pf_k[u]) * DIM + pf_c];
        }
        const float* Wt = &Ws[buf * BK * DIM];
        // X for next tile is loaded after compute (Xs rewritten needs sync) ->
        // instead stage X for tile t+1 into registers now, store after sync:
        float4 xn0, xn1;
        if (t + 1 < 16) {
            xn0 = *(const float4*)&data[(size_t)(row0 + px_r0) * DIM + (t + 1) * BK + px_q0];
            xn1 = *(const float4*)&data[(size_t)(row0 + px_r0) * DIM + (t + 1) * BK + px_q0 + 4];
        }
        #pragma unroll
        for (int kk = 0; kk < BK; kk++) {
            u64 bq[4];
            #pragma unroll
            for (int p = 0; p < 4; p++)
                bq[p] = *(const u64*)&Wt[kk * DIM + tc * 2 + 64 * p];
            #pragma unroll
            for (int i = 0; i < RPW; i++) {
                u64 a2 = dup2(Xs[(wd * RPW + i) * BK + kk]);
                #pragma unroll
                for (int p = 0; p < 4; p++) FMA2(acc[i][p], a2, bq[p]);
            }
        }
        __syncthreads();   // Xs rewrite barrier
        if (t + 1 < 16) {
            *(float4*)&Xs[px_r0 * BK + px_q0]     = xn0;
            *(float4*)&Xs[px_r0 * BK + px_q0 + 4] = xn1;
        }
    }
    // epilogue: omega column, bias, relu -> Hs
    {
        float aom[RPW];
        #pragma unroll
        for (int i = 0; i < RPW; i++) aom[i] = omega[row0 + wd * RPW + i];
        #pragma unroll
        for (int p = 0; p < 4; p++) {
            int c = tc * 2 + 64 * p;
            float2 bom = *(const float2*)&W1[(size_t)256 * DIM + c];
            float2 bb  = *(const float2*)&b1[c];
            #pragma unroll
            for (int i = 0; i < RPW; i++) {
                float lo, hi; unpk(acc[i][p], lo, hi);
                float2 o;
                o.x = fmaxf(fmaf(aom[i], bom.x, lo) + bb.x, 0.f);
                o.y = fmaxf(fmaf(aom[i], bom.y, hi) + bb.y, 0.f);
                *(float2*)&Hs[(wd * RPW + i) * DIM + c] = o;
            }
        }
    }
    __syncthreads();

    // =======================================================================
    // Stage 2: Hs = relu(Hs @ W2 + b2)
    // =======================================================================
    #pragma unroll
    for (int i = 0; i < RPW; i++)
        #pragma unroll
        for (int p = 0; p < 4; p++) acc[i][p] = 0ull;

    #pragma unroll
    for (int u = 0; u < 4; u++)
        wreg[u] = *(const float4*)&W2[(size_t)pf_k[u] * DIM + pf_c];
    #pragma unroll
    for (int u = 0; u < 4; u++)
        *(float4*)&Ws[pf_k[u] * DIM + pf_c] = wreg[u];
    #pragma unroll
    for (int u = 0; u < 4; u++)
        wreg[u] = *(const float4*)&W2[(size_t)(BK + pf_k[u]) * DIM + pf_c];

    for (int t = 0; t < 16; t++) {
        const int buf = t & 1;
        if (t > 0) {
            #pragma unroll
            for (int u = 0; u < 4; u++)
                *(float4*)&Ws[buf * BK * DIM + pf_k[u] * DIM + pf_c] = wreg[u];
        }
        __syncthreads();
        if (t + 1 < 16) {
            #pragma unroll
            for (int u = 0; u < 4; u++)
                wreg[u] = *(const float4*)&W2[(size_t)((t + 1) * BK + pf_k[u]) * DIM + pf_c];
        }
        const float* Wt = &Ws[buf * BK * DIM];
        const int k0 = t * BK;
        #pragma unroll
        for (int kk = 0; kk < BK; kk++) {
            u64 bq[4];
            #pragma unroll
            for (int p = 0; p < 4; p++)
                bq[p] = *(const u64*)&Wt[kk * DIM + tc * 2 + 64 * p];
            #pragma unroll
            for (int i = 0; i < RPW; i++) {
                u64 a2 = dup2(Hs[(wd * RPW + i) * DIM + k0 + kk]);
                #pragma unroll
                for (int p = 0; p < 4; p++) FMA2(acc[i][p], a2, bq[p]);
            }
        }
    }
    __syncthreads();   // all compute done before Hs overwrite
    {
        #pragma unroll
        for (int p = 0; p < 4; p++) {
            int c = tc * 2 + 64 * p;
            float2 bb = *(const float2*)&b2[c];
            #pragma unroll
            for (int i = 0; i < RPW; i++) {
                float lo, hi; unpk(acc[i][p], lo, hi);
                float2 o;
                o.x = fmaxf(lo + bb.x, 0.f);
                o.y = fmaxf(hi + bb.y, 0.f);
                *(float2*)&Hs[(wd * RPW + i) * DIM + c] = o;
            }
        }
    }
    __syncthreads();

    // =======================================================================
    // Stage 3: Hs = relu(Hs @ [Wm1|Wl1] + [bm1|bl1])
    // =======================================================================
    #pragma unroll
    for (int i = 0; i < RPW; i++)
        #pragma unroll
        for (int p = 0; p < 4; p++) acc[i][p] = 0ull;

    const int s3c = (pf_c < 128) ? pf_c : pf_c - 128;
    const float* S3 = (pf_c < 128) ? Wm1 : Wl1;

    #pragma unroll
    for (int u = 0; u < 4; u++)
        wreg[u] = *(const float4*)&S3[(size_t)pf_k[u] * 128 + s3c];
    #pragma unroll
    for (int u = 0; u < 4; u++)
        *(float4*)&Ws[pf_k[u] * DIM + pf_c] = wreg[u];
    #pragma unroll
    for (int u = 0; u < 4; u++)
        wreg[u] = *(const float4*)&S3[(size_t)(BK + pf_k[u]) * 128 + s3c];

    for (int t = 0; t < 16; t++) {
        const int buf = t & 1;
        if (t > 0) {
            #pragma unroll
            for (int u = 0; u < 4; u++)
                *(float4*)&Ws[buf * BK * DIM + pf_k[u] * DIM + pf_c] = wreg[u];
        }
        __syncthreads();
        if (t + 1 < 16) {
            #pragma unroll
            for (int u = 0; u < 4; u++)
                wreg[u] = *(const float4*)&S3[(size_t)((t + 1) * BK + pf_k[u]) * 128 + s3c];
        }
        const float* Wt = &Ws[buf * BK * DIM];
        const int k0 = t * BK;
        #pragma unroll
        for (int kk = 0; kk < BK; kk++) {
            u64 bq[4];
            #pragma unroll
            for (int p = 0; p < 4; p++)
                bq[p] = *(const u64*)&Wt[kk * DIM + tc * 2 + 64 * p];
            #pragma unroll
            for (int i = 0; i < RPW; i++) {
                u64 a2 = dup2(Hs[(wd * RPW + i) * DIM + k0 + kk]);
                #pragma unroll
                for (int p = 0; p < 4; p++) FMA2(acc[i][p], a2, bq[p]);
            }
        }
    }
    __syncthreads();
    {
        #pragma unroll
        for (int p = 0; p < 4; p++) {
            int c = tc * 2 + 64 * p;
            float2 bb;
            if (c < 128) bb = *(const float2*)&bm1[c];
            else         bb = *(const float2*)&bl1[c - 128];
            #pragma unroll
            for (int i = 0; i < RPW; i++) {
                float lo, hi; unpk(acc[i][p], lo, hi);
                float2 o;
                o.x = fmaxf(lo + bb.x, 0.f);
                o.y = fmaxf(hi + bb.y, 0.f);
                *(float2*)&Hs[(wd * RPW + i) * DIM + c] = o;
            }
        }
    }
    __syncthreads();

    // ===================== Stage 4: head reductions ========================
    const float bm2v = bm2[0];
    const float bl2v = bl2[0];
    #pragma unroll 1
    for (int q = 0; q < RPW; q++) {
        int r = wd * RPW + q;
        float s1 = 0.f, s2 = 0.f;
        #pragma unroll
        for (int m = 0; m < 4; m++) {
            int h = tc + 32 * m;
            s1 = fmaf(Hs[r * DIM + h],       __ldg(&Wm2[h]), s1);
            s2 = fmaf(Hs[r * DIM + 128 + h], __ldg(&Wl2[h]), s2);
        }
        #pragma unroll
        for (int o = 16; o > 0; o >>= 1) {
            s1 += __shfl_xor_sync(0xffffffffu, s1, o);
            s2 += __shfl_xor_sync(0xffffffffu, s2, o);
        }
        if (tc == 0) {
            int gr = row0 + r;
            float pm = s1 + bm2v;
            float lv = s2 + bl2v;
            float xm = fmaxf(pm, 0.f) + log1pf(expf(-fabsf(pm)));
            float xi = xm + expf(0.5f * lv) * eps[gr];
            xi = fminf(fmaxf(xi, 0.f), 1.f);
            out[gr]            = xm;   // xi_mean
            out[N_ROWS + gr]   = lv;   // xi_lnvar
            g_xi[gr]           = xi;
        }
    }
}

// ---------------------------------------------------------------------------
// Scan kernel v3: EIGHT threads per row (8 hidden units each), 1024-thread
// blocks -> 32 warps/SM for latency hiding. 3-level shfl butterfly reduce.
// ---------------------------------------------------------------------------
#define SRPB 128

__global__ __launch_bounds__(1024, 1)
void scan_kernel(const float* __restrict__ data,
                 const float* __restrict__ omega,
                 const float* __restrict__ Wa1, const float* __restrict__ ba1,
                 const float* __restrict__ Wa2, const float* __restrict__ ba2,
                 float* __restrict__ out)
{
    __shared__ float ytile[SRPB][33];

    const int tid = threadIdx.x;
    const int l8  = tid & 7;                   // sub-lane within row group
    const int r   = tid >> 3;                  // local row (0..127)
    const int row = blockIdx.x * SRPB + r;

    // this thread's 8 hidden units: j = l8*8 + i
    float w[8], v[8], c[8];
    const float om = omega[row];
    #pragma unroll
    for (int i = 0; i < 8; i++) {
        int j = l8 * 8 + i;
        w[i] = Wa1[64 + j];
        v[i] = Wa2[j];
        c[i] = fmaf(om, Wa1[j], ba1[j]);
    }
    const float b2v = ba2[0];

    float y  = data[(size_t)row * DIM];
    float vv = 0.f;
    const float xi = g_xi[row];
    const float dm = expf(-xi * DT_F);
    float f = 1.f;

    float* __restrict__ xout = out + 2 * N_ROWS;

    for (int t = 0; t < 256; t++) {
        if (l8 == 0) ytile[r][t & 31] = f * y;

        float a0 = 0.f, a1 = 0.f;
        #pragma unroll
        for (int i = 0; i < 8; i += 2) {
            a0 = fmaf(fmaxf(fmaf(y, w[i + 0], c[i + 0]), 0.f), v[i + 0], a0);
            a1 = fmaf(fmaxf(fmaf(y, w[i + 1], c[i + 1]), 0.f), v[i + 1], a1);
        }
        float acc = a0 + a1;
        acc += __shfl_xor_sync(0xffffffffu, acc, 1);
        acc += __shfl_xor_sync(0xffffffffu, acc, 2);
        acc += __shfl_xor_sync(0xffffffffu, acc, 4);
        acc += b2v;

        float ynew = fmaf(DT_F, vv, y);
        vv = fmaf(DT_F, acc, vv);
        y  = ynew;
        f *= dm;

        if ((t & 31) == 31) {
            __syncthreads();
            int tb = t - 31;
            #pragma unroll
            for (int i = 0; i < 4; i++) {
                int idx = i * 1024 + tid;      // 0..4095 over 128x32 tile
                int rr  = idx >> 5;
                int cc  = idx & 31;
                xout[(size_t)(blockIdx.x * SRPB + rr) * DIM + tb + cc] =
                    ytile[rr][cc];
            }
            __syncthreads();
        }
    }
}

// ---------------------------------------------------------------------------
extern "C" void kernel_launch(void* const* d_in, const int* in_sizes, int n_in,
                              void* d_out, int out_size)
{
    const float* data = (const float*)d_in[0];
    const float* omega= (const float*)d_in[1];
    const float* eps  = (const float*)d_in[2];
    const float* W1   = (const float*)d_in[3];  const float* b1  = (const float*)d_in[4];
    const float* W2   = (const float*)d_in[5];  const float* b2  = (const float*)d_in[6];
    const float* Wm1  = (const float*)d_in[7];  const float* bm1 = (const float*)d_in[8];
    const float* Wm2  = (const float*)d_in[9];  const float* bm2 = (const float*)d_in[10];
    const float* Wl1  = (const float*)d_in[11]; const float* bl1 = (const float*)d_in[12];
    const float* Wl2  = (const float*)d_in[13]; const float* bl2 = (const float*)d_in[14];
    const float* Wa1  = (const float*)d_in[15]; const float* ba1 = (const float*)d_in[16];
    const float* Wa2  = (const float*)d_in[17]; const float* ba2 = (const float*)d_in[18];
    float* out = (float*)d_out;

    cudaFuncSetAttribute(mlp_kernel,
                         cudaFuncAttributeMaxDynamicSharedMemorySize, MLP_SMEM);

    mlp_kernel<<<N_ROWS / ROWS, 256, MLP_SMEM>>>(
        data, omega, eps, W1, b1, W2, b2,
        Wm1, bm1, Wm2, bm2, Wl1, bl1, Wl2, bl2, out);

    scan_kernel<<<N_ROWS / SRPB, 1024>>>(data, omega, Wa1, ba1, Wa2, ba2, out);
}

// round 12
// speedup vs baseline: 1.0624x; 1.0624x over previous
#include <cuda_runtime.h>
#include <math.h>
#include <stdint.h>

#define N_ROWS 16384
#define DIM 256
#define DT_F 0.01f

// scratch for xi (clipped), passed from MLP kernel to scan kernel
__device__ float g_xi[N_ROWS];

typedef unsigned long long u64;

#define FMA2(acc, a2, b2) \
    asm("fma.rn.f32x2 %0, %1, %2, %3;" : "=l"(acc) : "l"(a2), "l"(b2), "l"(acc))
#define FMA2O(d, a2, b2, c2) \
    asm("fma.rn.f32x2 %0, %1, %2, %3;" : "=l"(d) : "l"(a2), "l"(b2), "l"(c2))

__device__ __forceinline__ u64 dup2(float a) {
    u64 r; uint32_t au = __float_as_uint(a);
    asm("mov.b64 %0, {%1, %1};" : "=l"(r) : "r"(au));
    return r;
}
__device__ __forceinline__ u64 pack2(float lo, float hi) {
    u64 r;
    asm("mov.b64 %0, {%1, %2};" : "=l"(r)
        : "r"(__float_as_uint(lo)), "r"(__float_as_uint(hi)));
    return r;
}
__device__ __forceinline__ void unpk(u64 x, float& lo, float& hi) {
    uint32_t l, h;
    asm("mov.b64 {%0, %1}, %2;" : "=r"(l), "=r"(h) : "l"(x));
    lo = __uint_as_float(l); hi = __uint_as_float(h);
}
// packed relu via scalar FMNMX on the two halves (mov.b64 pack/unpack is
// register-pair bookkeeping that ptxas eliminates)
__device__ __forceinline__ u64 relu2(u64 x) {
    float lo, hi; unpk(x, lo, hi);
    return pack2(fmaxf(lo, 0.f), fmaxf(hi, 0.f));
}

// ---------------------------------------------------------------------------
// Fused MLP kernel: 128 rows per block, 256 threads (8 warps x 16 rows each),
// packed f32x2 FFMA. Hs doubles as the stage-1 input tile (data preloaded),
// so all 3 stages share one uniform inner loop; A-operands via LDS.64 kk-pairs.
// ---------------------------------------------------------------------------
#define ROWS 128
#define BK   16
#define RPW  16     // rows per warp (= rows per thread)
#define OFF_WS (ROWS * DIM)
#define MLP_SMEM ((ROWS * DIM + 2 * BK * DIM) * 4)

extern __shared__ float smem[];

__global__ __launch_bounds__(256, 1)
void mlp_kernel(const float* __restrict__ data,
                const float* __restrict__ omega,
                const float* __restrict__ eps,
                const float* __restrict__ W1,  const float* __restrict__ b1,
                const float* __restrict__ W2,  const float* __restrict__ b2,
                const float* __restrict__ Wm1, const float* __restrict__ bm1,
                const float* __restrict__ Wm2, const float* __restrict__ bm2,
                const float* __restrict__ Wl1, const float* __restrict__ bl1,
                const float* __restrict__ Wl2, const float* __restrict__ bl2,
                float* __restrict__ out)
{
    float* Hs = smem;                        // 128 x 256 (data, then activations)
    float* Ws = smem + OFF_WS;               // 2 x (16 x 256)

    const int tid = threadIdx.x;
    const int tc  = tid & 31;                // lane -> column pairs tc*2 + 64p
    const int wd  = tid >> 5;                // warp id -> rows wd*16 .. +15
    const int row0 = blockIdx.x * ROWS;

    // W-tile prefetch: BK x 256 floats = 1024 float4; 256 threads x 4
    const int pf_k[4] = { tid >> 6, (tid + 256) >> 6, (tid + 512) >> 6, (tid + 768) >> 6 };
    const int pf_c = (tid & 63) * 4;

    u64 acc[RPW][4];
    float4 wreg[4];

    // preload data tile into Hs: 128 rows x 64 float4 = 8192 float4, 256 thr x 32
    #pragma unroll
    for (int u = 0; u < 32; u++) {
        int idx = tid + u * 256;             // float4 idx 0..8191
        int r = idx >> 6;
        int c4 = (idx & 63) * 4;
        *(float4*)&Hs[r * DIM + c4] =
            *(const float4*)&data[(size_t)(row0 + r) * DIM + c4];
    }
    __syncthreads();

    // =============== the 3 GEMM stages share this inner-loop shape ==========
    #define GEMM_TILE(Wt, k0)                                                   \
        _Pragma("unroll")                                                       \
        for (int kq = 0; kq < BK / 2; kq++) {                                   \
            u64 bq0[4], bq1[4];                                                 \
            _Pragma("unroll")                                                   \
            for (int p = 0; p < 4; p++) {                                       \
                bq0[p] = *(const u64*)&(Wt)[(2*kq)     * DIM + tc * 2 + 64 * p];\
                bq1[p] = *(const u64*)&(Wt)[(2*kq + 1) * DIM + tc * 2 + 64 * p];\
            }                                                                   \
            _Pragma("unroll")                                                   \
            for (int i = 0; i < RPW; i++) {                                     \
                u64 a01 = *(const u64*)&Hs[(wd * RPW + i) * DIM + (k0) + 2*kq]; \
                float alo, ahi; unpk(a01, alo, ahi);                            \
                u64 a2l = dup2(alo), a2h = dup2(ahi);                           \
                _Pragma("unroll")                                               \
                for (int p = 0; p < 4; p++) {                                   \
                    FMA2(acc[i][p], a2l, bq0[p]);                               \
                    FMA2(acc[i][p], a2h, bq1[p]);                               \
                }                                                               \
            }                                                                   \
        }

    // =======================================================================
    // Stage 1: Hs = relu([data|omega] @ W1 + b1)
    // =======================================================================
    #pragma unroll
    for (int i = 0; i < RPW; i++)
        #pragma unroll
        for (int p = 0; p < 4; p++) acc[i][p] = 0ull;

    #pragma unroll
    for (int u = 0; u < 4; u++)
        wreg[u] = *(const float4*)&W1[(size_t)pf_k[u] * DIM + pf_c];
    #pragma unroll
    for (int u = 0; u < 4; u++)
        *(float4*)&Ws[pf_k[u] * DIM + pf_c] = wreg[u];
    #pragma unroll
    for (int u = 0; u < 4; u++)
        wreg[u] = *(const float4*)&W1[(size_t)(BK + pf_k[u]) * DIM + pf_c];

    for (int t = 0; t < 16; t++) {
        const int buf = t & 1;
        if (t > 0) {
            #pragma unroll
            for (int u = 0; u < 4; u++)
                *(float4*)&Ws[buf * BK * DIM + pf_k[u] * DIM + pf_c] = wreg[u];
        }
        __syncthreads();
        if (t + 1 < 16) {
            #pragma unroll
            for (int u = 0; u < 4; u++)
                wreg[u] = *(const float4*)&W1[(size_t)((t + 1) * BK + pf_k[u]) * DIM + pf_c];
        }
        const float* Wt = &Ws[buf * BK * DIM];
        GEMM_TILE(Wt, t * BK)
    }
    __syncthreads();
    // epilogue: omega column (k=256), bias, relu -> Hs (own rows only)
    {
        float aom[RPW];
        #pragma unroll
        for (int i = 0; i < RPW; i++) aom[i] = omega[row0 + wd * RPW + i];
        #pragma unroll
        for (int p = 0; p < 4; p++) {
            int c = tc * 2 + 64 * p;
            u64 bom = *(const u64*)&W1[(size_t)256 * DIM + c];
            float2 bb = *(const float2*)&b1[c];
            #pragma unroll
            for (int i = 0; i < RPW; i++) {
                u64 s;
                FMA2O(s, dup2(aom[i]), bom, acc[i][p]);
                float lo, hi; unpk(s, lo, hi);
                float2 o;
                o.x = fmaxf(lo + bb.x, 0.f);
                o.y = fmaxf(hi + bb.y, 0.f);
                *(float2*)&Hs[(wd * RPW + i) * DIM + c] = o;
            }
        }
    }
    __syncthreads();

    // =======================================================================
    // Stage 2: Hs = relu(Hs @ W2 + b2)
    // =======================================================================
    #pragma unroll
    for (int i = 0; i < RPW; i++)
        #pragma unroll
        for (int p = 0; p < 4; p++) acc[i][p] = 0ull;

    #pragma unroll
    for (int u = 0; u < 4; u++)
        wreg[u] = *(const float4*)&W2[(size_t)pf_k[u] * DIM + pf_c];
    #pragma unroll
    for (int u = 0; u < 4; u++)
        *(float4*)&Ws[pf_k[u] * DIM + pf_c] = wreg[u];
    #pragma unroll
    for (int u = 0; u < 4; u++)
        wreg[u] = *(const float4*)&W2[(size_t)(BK + pf_k[u]) * DIM + pf_c];

    for (int t = 0; t < 16; t++) {
        const int buf = t & 1;
        if (t > 0) {
            #pragma unroll
            for (int u = 0; u < 4; u++)
                *(float4*)&Ws[buf * BK * DIM + pf_k[u] * DIM + pf_c] = wreg[u];
        }
        __syncthreads();
        if (t + 1 < 16) {
            #pragma unroll
            for (int u = 0; u < 4; u++)
                wreg[u] = *(const float4*)&W2[(size_t)((t + 1) * BK + pf_k[u]) * DIM + pf_c];
        }
        const float* Wt = &Ws[buf * BK * DIM];
        GEMM_TILE(Wt, t * BK)
    }
    __syncthreads();
    {
        #pragma unroll
        for (int p = 0; p < 4; p++) {
            int c = tc * 2 + 64 * p;
            float2 bb = *(const float2*)&b2[c];
            #pragma unroll
            for (int i = 0; i < RPW; i++) {
                float lo, hi; unpk(acc[i][p], lo, hi);
                float2 o;
                o.x = fmaxf(lo + bb.x, 0.f);
                o.y = fmaxf(hi + bb.y, 0.f);
                *(float2*)&Hs[(wd * RPW + i) * DIM + c] = o;
            }
        }
    }
    __syncthreads();

    // =======================================================================
    // Stage 3: Hs = relu(Hs @ [Wm1|Wl1] + [bm1|bl1])
    // =======================================================================
    #pragma unroll
    for (int i = 0; i < RPW; i++)
        #pragma unroll
        for (int p = 0; p < 4; p++) acc[i][p] = 0ull;

    const int s3c = (pf_c < 128) ? pf_c : pf_c - 128;
    const float* S3 = (pf_c < 128) ? Wm1 : Wl1;

    #pragma unroll
    for (int u = 0; u < 4; u++)
        wreg[u] = *(const float4*)&S3[(size_t)pf_k[u] * 128 + s3c];
    #pragma unroll
    for (int u = 0; u < 4; u++)
        *(float4*)&Ws[pf_k[u] * DIM + pf_c] = wreg[u];
    #pragma unroll
    for (int u = 0; u < 4; u++)
        wreg[u] = *(const float4*)&S3[(size_t)(BK + pf_k[u]) * 128 + s3c];

    for (int t = 0; t < 16; t++) {
        const int buf = t & 1;
        if (t > 0) {
            #pragma unroll
            for (int u = 0; u < 4; u++)
                *(float4*)&Ws[buf * BK * DIM + pf_k[u] * DIM + pf_c] = wreg[u];
        }
        __syncthreads();
        if (t + 1 < 16) {
            #pragma unroll
            for (int u = 0; u < 4; u++)
                wreg[u] = *(const float4*)&S3[(size_t)((t + 1) * BK + pf_k[u]) * 128 + s3c];
        }
        const float* Wt = &Ws[buf * BK * DIM];
        GEMM_TILE(Wt, t * BK)
    }
    __syncthreads();
    {
        #pragma unroll
        for (int p = 0; p < 4; p++) {
            int c = tc * 2 + 64 * p;
            float2 bb;
            if (c < 128) bb = *(const float2*)&bm1[c];
            else         bb = *(const float2*)&bl1[c - 128];
            #pragma unroll
            for (int i = 0; i < RPW; i++) {
                float lo, hi; unpk(acc[i][p], lo, hi);
                float2 o;
                o.x = fmaxf(lo + bb.x, 0.f);
                o.y = fmaxf(hi + bb.y, 0.f);
                *(float2*)&Hs[(wd * RPW + i) * DIM + c] = o;
            }
        }
    }
    __syncthreads();

    // ===================== Stage 4: head reductions ========================
    const float bm2v = bm2[0];
    const float bl2v = bl2[0];
    #pragma unroll 1
    for (int q = 0; q < RPW; q++) {
        int r = wd * RPW + q;
        float s1 = 0.f, s2 = 0.f;
        #pragma unroll
        for (int m = 0; m < 4; m++) {
            int h = tc + 32 * m;
            s1 = fmaf(Hs[r * DIM + h],       __ldg(&Wm2[h]), s1);
            s2 = fmaf(Hs[r * DIM + 128 + h], __ldg(&Wl2[h]), s2);
        }
        #pragma unroll
        for (int o = 16; o > 0; o >>= 1) {
            s1 += __shfl_xor_sync(0xffffffffu, s1, o);
            s2 += __shfl_xor_sync(0xffffffffu, s2, o);
        }
        if (tc == 0) {
            int gr = row0 + r;
            float pm = s1 + bm2v;
            float lv = s2 + bl2v;
            float xm = fmaxf(pm, 0.f) + log1pf(expf(-fabsf(pm)));
            float xi = xm + expf(0.5f * lv) * eps[gr];
            xi = fminf(fmaxf(xi, 0.f), 1.f);
            out[gr]            = xm;   // xi_mean
            out[N_ROWS + gr]   = lv;   // xi_lnvar
            g_xi[gr]           = xi;
        }
    }
}

// ---------------------------------------------------------------------------
// Scan kernel v4: FOUR threads per row, 16 units each packed as 8 f32x2 pairs.
// Inner step: 8x(FMA2 + 2 FMNMX + FMA2) + unpack + 2 shfl. All regs.
// ---------------------------------------------------------------------------
#define SRPB 128

__global__ __launch_bounds__(512, 1)
void scan_kernel(const float* __restrict__ data,
                 const float* __restrict__ omega,
                 const float* __restrict__ Wa1, const float* __restrict__ ba1,
                 const float* __restrict__ Wa2, const float* __restrict__ ba2,
                 float* __restrict__ out)
{
    __shared__ float ytile[SRPB][33];

    const int tid = threadIdx.x;
    const int l4  = tid & 3;
    const int r   = tid >> 2;
    const int row = blockIdx.x * SRPB + r;

    // this thread's 16 hidden units as 8 pairs: j = l4*16 + 2q
    u64 w2[8], v2[8], c2[8];
    const float om = omega[row];
    #pragma unroll
    for (int q = 0; q < 8; q++) {
        int j = l4 * 16 + 2 * q;
        float2 wf = *(const float2*)&Wa1[64 + j];
        float2 vf = *(const float2*)&Wa2[j];
        w2[q] = pack2(wf.x, wf.y);
        v2[q] = pack2(vf.x, vf.y);
        c2[q] = pack2(fmaf(om, Wa1[j],     ba1[j]),
                      fmaf(om, Wa1[j + 1], ba1[j + 1]));
    }
    const float b2v = ba2[0];

    float y  = data[(size_t)row * DIM];
    float vv = 0.f;
    const float xi = g_xi[row];
    const float dm = expf(-xi * DT_F);
    float f = 1.f;

    float* __restrict__ xout = out + 2 * N_ROWS;

    for (int t = 0; t < 256; t++) {
        if (l4 == 0) ytile[r][t & 31] = f * y;

        u64 y2 = dup2(y);
        u64 acc2a = 0ull, acc2b = 0ull;
        #pragma unroll
        for (int q = 0; q < 8; q += 2) {
            u64 h0, h1;
            FMA2O(h0, y2, w2[q],     c2[q]);
            FMA2O(h1, y2, w2[q + 1], c2[q + 1]);
            FMA2(acc2a, relu2(h0), v2[q]);
            FMA2(acc2b, relu2(h1), v2[q + 1]);
        }
        float alo, ahi, blo, bhi;
        unpk(acc2a, alo, ahi);
        unpk(acc2b, blo, bhi);
        float acc = (alo + ahi) + (blo + bhi);
        acc += __shfl_xor_sync(0xffffffffu, acc, 1);
        acc += __shfl_xor_sync(0xffffffffu, acc, 2);
        acc += b2v;

        float ynew = fmaf(DT_F, vv, y);
        vv = fmaf(DT_F, acc, vv);
        y  = ynew;
        f *= dm;

        if ((t & 31) == 31) {
            __syncthreads();
            int tb = t - 31;
            #pragma unroll
            for (int i = 0; i < 8; i++) {
                int idx = i * 512 + tid;
                int rr  = idx >> 5;
                int cc  = idx & 31;
                xout[(size_t)(blockIdx.x * SRPB + rr) * DIM + tb + cc] =
                    ytile[rr][cc];
            }
            __syncthreads();
        }
    }
}

// ---------------------------------------------------------------------------
extern "C" void kernel_launch(void* const* d_in, const int* in_sizes, int n_in,
                              void* d_out, int out_size)
{
    const float* data = (const float*)d_in[0];
    const float* omega= (const float*)d_in[1];
    const float* eps  = (const float*)d_in[2];
    const float* W1   = (const float*)d_in[3];  const float* b1  = (const float*)d_in[4];
    const float* W2   = (const float*)d_in[5];  const float* b2  = (const float*)d_in[6];
    const float* Wm1  = (const float*)d_in[7];  const float* bm1 = (const float*)d_in[8];
    const float* Wm2  = (const float*)d_in[9];  const float* bm2 = (const float*)d_in[10];
    const float* Wl1  = (const float*)d_in[11]; const float* bl1 = (const float*)d_in[12];
    const float* Wl2  = (const float*)d_in[13]; const float* bl2 = (const float*)d_in[14];
    const float* Wa1  = (const float*)d_in[15]; const float* ba1 = (const float*)d_in[16];
    const float* Wa2  = (const float*)d_in[17]; const float* ba2 = (const float*)d_in[18];
    float* out = (float*)d_out;

    cudaFuncSetAttribute(mlp_kernel,
                         cudaFuncAttributeMaxDynamicSharedMemorySize, MLP_SMEM);

    mlp_kernel<<<N_ROWS / ROWS, 256, MLP_SMEM>>>(
        data, omega, eps, W1, b1, W2, b2,
        Wm1, bm1, Wm2, bm2, Wl1, bl1, Wl2, bl2, out);

    scan_kernel<<<N_ROWS / SRPB, 512>>>(data, omega, Wa1, ba1, Wa2, ba2, out);
}

// round 14
// speedup vs baseline: 1.1632x; 1.0948x over previous
#include <cuda_runtime.h>
#include <math.h>
#include <stdint.h>

#define N_ROWS 16384
#define DIM 256
#define DT_F 0.01f

// row tiling: 112 rows/block, grid 147 (146*112=16352, last block 32 valid rows)
#define BROWS 112
#define GRID_N 147

// scratch for xi (clipped), passed from MLP kernel to scan kernel
__device__ float g_xi[N_ROWS];

typedef unsigned long long u64;

#define FMA2(acc, a2, b2) \
    asm("fma.rn.f32x2 %0, %1, %2, %3;" : "=l"(acc) : "l"(a2), "l"(b2), "l"(acc))
#define FMA2O(d, a2, b2, c2) \
    asm("fma.rn.f32x2 %0, %1, %2, %3;" : "=l"(d) : "l"(a2), "l"(b2), "l"(c2))

__device__ __forceinline__ u64 dup2(float a) {
    u64 r; uint32_t au = __float_as_uint(a);
    asm("mov.b64 %0, {%1, %1};" : "=l"(r) : "r"(au));
    return r;
}
__device__ __forceinline__ u64 pack2(float lo, float hi) {
    u64 r;
    asm("mov.b64 %0, {%1, %2};" : "=l"(r)
        : "r"(__float_as_uint(lo)), "r"(__float_as_uint(hi)));
    return r;
}
__device__ __forceinline__ void unpk(u64 x, float& lo, float& hi) {
    uint32_t l, h;
    asm("mov.b64 {%0, %1}, %2;" : "=r"(l), "=r"(h) : "l"(x));
    lo = __uint_as_float(l); hi = __uint_as_float(h);
}
__device__ __forceinline__ u64 relu2(u64 x) {
    float lo, hi; unpk(x, lo, hi);
    return pack2(fmaxf(lo, 0.f), fmaxf(hi, 0.f));
}

// ---------------------------------------------------------------------------
// Fused MLP kernel: 112 rows per block, 256 threads (8 warps x 14 rows each),
// packed f32x2 FFMA. Hs doubles as the stage-1 input tile (data preloaded).
// Out-of-range rows (last block): loads clamped, stores guarded.
// ---------------------------------------------------------------------------
#define BK   16
#define RPW  14     // rows per warp (= rows per thread)
#define OFF_WS (BROWS * DIM)
#define MLP_SMEM ((BROWS * DIM + 2 * BK * DIM) * 4)

extern __shared__ float smem[];

__global__ __launch_bounds__(256, 1)
void mlp_kernel(const float* __restrict__ data,
                const float* __restrict__ omega,
                const float* __restrict__ eps,
                const float* __restrict__ W1,  const float* __restrict__ b1,
                const float* __restrict__ W2,  const float* __restrict__ b2,
                const float* __restrict__ Wm1, const float* __restrict__ bm1,
                const float* __restrict__ Wm2, const float* __restrict__ bm2,
                const float* __restrict__ Wl1, const float* __restrict__ bl1,
                const float* __restrict__ Wl2, const float* __restrict__ bl2,
                float* __restrict__ out)
{
    float* Hs = smem;                        // 112 x 256 (data, then activations)
    float* Ws = smem + OFF_WS;               // 2 x (16 x 256)

    const int tid = threadIdx.x;
    const int tc  = tid & 31;                // lane -> column pairs tc*2 + 64p
    const int wd  = tid >> 5;                // warp id -> rows wd*14 .. +13
    const int row0 = blockIdx.x * BROWS;

    // W-tile prefetch: BK x 256 floats = 1024 float4; 256 threads x 4
    const int pf_k[4] = { tid >> 6, (tid + 256) >> 6, (tid + 512) >> 6, (tid + 768) >> 6 };
    const int pf_c = (tid & 63) * 4;

    u64 acc[RPW][4];
    float4 wreg[4];

    // preload data tile into Hs: 112 rows x 64 float4 = 7168 float4, 256 thr x 28
    #pragma unroll
    for (int u = 0; u < 28; u++) {
        int idx = tid + u * 256;             // float4 idx 0..7167
        int r = idx >> 6;
        int c4 = (idx & 63) * 4;
        int gr = min(row0 + r, N_ROWS - 1);
        *(float4*)&Hs[r * DIM + c4] =
            *(const float4*)&data[(size_t)gr * DIM + c4];
    }
    __syncthreads();

    // =============== the 3 GEMM stages share this inner-loop shape ==========
    #define GEMM_TILE(Wt, k0)                                                   \
        _Pragma("unroll")                                                       \
        for (int kq = 0; kq < BK / 2; kq++) {                                   \
            u64 bq0[4], bq1[4];                                                 \
            _Pragma("unroll")                                                   \
            for (int p = 0; p < 4; p++) {                                       \
                bq0[p] = *(const u64*)&(Wt)[(2*kq)     * DIM + tc * 2 + 64 * p];\
                bq1[p] = *(const u64*)&(Wt)[(2*kq + 1) * DIM + tc * 2 + 64 * p];\
            }                                                                   \
            _Pragma("unroll")                                                   \
            for (int i = 0; i < RPW; i++) {                                     \
                u64 a01 = *(const u64*)&Hs[(wd * RPW + i) * DIM + (k0) + 2*kq]; \
                float alo, ahi; unpk(a01, alo, ahi);                            \
                u64 a2l = dup2(alo), a2h = dup2(ahi);                           \
                _Pragma("unroll")                                               \
                for (int p = 0; p < 4; p++) {                                   \
                    FMA2(acc[i][p], a2l, bq0[p]);                               \
                    FMA2(acc[i][p], a2h, bq1[p]);                               \
                }                                                               \
            }                                                                   \
        }

    // =======================================================================
    // Stage 1: Hs = relu([data|omega] @ W1 + b1)
    // =======================================================================
    #pragma unroll
    for (int i = 0; i < RPW; i++)
        #pragma unroll
        for (int p = 0; p < 4; p++) acc[i][p] = 0ull;

    #pragma unroll
    for (int u = 0; u < 4; u++)
        wreg[u] = *(const float4*)&W1[(size_t)pf_k[u] * DIM + pf_c];
    #pragma unroll
    for (int u = 0; u < 4; u++)
        *(float4*)&Ws[pf_k[u] * DIM + pf_c] = wreg[u];
    #pragma unroll
    for (int u = 0; u < 4; u++)
        wreg[u] = *(const float4*)&W1[(size_t)(BK + pf_k[u]) * DIM + pf_c];

    for (int t = 0; t < 16; t++) {
        const int buf = t & 1;
        if (t > 0) {
            #pragma unroll
            for (int u = 0; u < 4; u++)
                *(float4*)&Ws[buf * BK * DIM + pf_k[u] * DIM + pf_c] = wreg[u];
        }
        __syncthreads();
        if (t + 1 < 16) {
            #pragma unroll
            for (int u = 0; u < 4; u++)
                wreg[u] = *(const float4*)&W1[(size_t)((t + 1) * BK + pf_k[u]) * DIM + pf_c];
        }
        const float* Wt = &Ws[buf * BK * DIM];
        GEMM_TILE(Wt, t * BK)
    }
    __syncthreads();
    // epilogue: omega column (k=256), bias, relu -> Hs (own rows only)
    {
        float aom[RPW];
        #pragma unroll
        for (int i = 0; i < RPW; i++)
            aom[i] = omega[min(row0 + wd * RPW + i, N_ROWS - 1)];
        #pragma unroll
        for (int p = 0; p < 4; p++) {
            int c = tc * 2 + 64 * p;
            u64 bom = *(const u64*)&W1[(size_t)256 * DIM + c];
            float2 bb = *(const float2*)&b1[c];
            #pragma unroll
            for (int i = 0; i < RPW; i++) {
                u64 s;
                FMA2O(s, dup2(aom[i]), bom, acc[i][p]);
                float lo, hi; unpk(s, lo, hi);
                float2 o;
                o.x = fmaxf(lo + bb.x, 0.f);
                o.y = fmaxf(hi + bb.y, 0.f);
                *(float2*)&Hs[(wd * RPW + i) * DIM + c] = o;
            }
        }
    }
    __syncthreads();

    // =======================================================================
    // Stage 2: Hs = relu(Hs @ W2 + b2)
    // =======================================================================
    #pragma unroll
    for (int i = 0; i < RPW; i++)
        #pragma unroll
        for (int p = 0; p < 4; p++) acc[i][p] = 0ull;

    #pragma unroll
    for (int u = 0; u < 4; u++)
        wreg[u] = *(const float4*)&W2[(size_t)pf_k[u] * DIM + pf_c];
    #pragma unroll
    for (int u = 0; u < 4; u++)
        *(float4*)&Ws[pf_k[u] * DIM + pf_c] = wreg[u];
    #pragma unroll
    for (int u = 0; u < 4; u++)
        wreg[u] = *(const float4*)&W2[(size_t)(BK + pf_k[u]) * DIM + pf_c];

    for (int t = 0; t < 16; t++) {
        const int buf = t & 1;
        if (t > 0) {
            #pragma unroll
            for (int u = 0; u < 4; u++)
                *(float4*)&Ws[buf * BK * DIM + pf_k[u] * DIM + pf_c] = wreg[u];
        }
        __syncthreads();
        if (t + 1 < 16) {
            #pragma unroll
            for (int u = 0; u < 4; u++)
                wreg[u] = *(const float4*)&W2[(size_t)((t + 1) * BK + pf_k[u]) * DIM + pf_c];
        }
        const float* Wt = &Ws[buf * BK * DIM];
        GEMM_TILE(Wt, t * BK)
    }
    __syncthreads();
    {
        #pragma unroll
        for (int p = 0; p < 4; p++) {
            int c = tc * 2 + 64 * p;
            float2 bb = *(const float2*)&b2[c];
            #pragma unroll
            for (int i = 0; i < RPW; i++) {
                float lo, hi; unpk(acc[i][p], lo, hi);
                float2 o;
                o.x = fmaxf(lo + bb.x, 0.f);
                o.y = fmaxf(hi + bb.y, 0.f);
                *(float2*)&Hs[(wd * RPW + i) * DIM + c] = o;
            }
        }
    }
    __syncthreads();

    // =======================================================================
    // Stage 3: Hs = relu(Hs @ [Wm1|Wl1] + [bm1|bl1])
    // =======================================================================
    #pragma unroll
    for (int i = 0; i < RPW; i++)
        #pragma unroll
        for (int p = 0; p < 4; p++) acc[i][p] = 0ull;

    const int s3c = (pf_c < 128) ? pf_c : pf_c - 128;
    const float* S3 = (pf_c < 128) ? Wm1 : Wl1;

    #pragma unroll
    for (int u = 0; u < 4; u++)
        wreg[u] = *(const float4*)&S3[(size_t)pf_k[u] * 128 + s3c];
    #pragma unroll
    for (int u = 0; u < 4; u++)
        *(float4*)&Ws[pf_k[u] * DIM + pf_c] = wreg[u];
    #pragma unroll
    for (int u = 0; u < 4; u++)
        wreg[u] = *(const float4*)&S3[(size_t)(BK + pf_k[u]) * 128 + s3c];

    for (int t = 0; t < 16; t++) {
        const int buf = t & 1;
        if (t > 0) {
            #pragma unroll
            for (int u = 0; u < 4; u++)
                *(float4*)&Ws[buf * BK * DIM + pf_k[u] * DIM + pf_c] = wreg[u];
        }
        __syncthreads();
        if (t + 1 < 16) {
            #pragma unroll
            for (int u = 0; u < 4; u++)
                wreg[u] = *(const float4*)&S3[(size_t)((t + 1) * BK + pf_k[u]) * 128 + s3c];
        }
        const float* Wt = &Ws[buf * BK * DIM];
        GEMM_TILE(Wt, t * BK)
    }
    __syncthreads();
    {
        #pragma unroll
        for (int p = 0; p < 4; p++) {
            int c = tc * 2 + 64 * p;
            float2 bb;
            if (c < 128) bb = *(const float2*)&bm1[c];
            else         bb = *(const float2*)&bl1[c - 128];
            #pragma unroll
            for (int i = 0; i < RPW; i++) {
                float lo, hi; unpk(acc[i][p], lo, hi);
                float2 o;
                o.x = fmaxf(lo + bb.x, 0.f);
                o.y = fmaxf(hi + bb.y, 0.f);
                *(float2*)&Hs[(wd * RPW + i) * DIM + c] = o;
            }
        }
    }
    __syncthreads();

    // ===================== Stage 4: head reductions ========================
    const float bm2v = bm2[0];
    const float bl2v = bl2[0];
    #pragma unroll 1
    for (int q = 0; q < RPW; q++) {
        int r = wd * RPW + q;
        float s1 = 0.f, s2 = 0.f;
        #pragma unroll
        for (int m = 0; m < 4; m++) {
            int h = tc + 32 * m;
            s1 = fmaf(Hs[r * DIM + h],       __ldg(&Wm2[h]), s1);
            s2 = fmaf(Hs[r * DIM + 128 + h], __ldg(&Wl2[h]), s2);
        }
        #pragma unroll
        for (int o = 16; o > 0; o >>= 1) {
            s1 += __shfl_xor_sync(0xffffffffu, s1, o);
            s2 += __shfl_xor_sync(0xffffffffu, s2, o);
        }
        int gr = row0 + r;
        if (tc == 0 && gr < N_ROWS) {
            float pm = s1 + bm2v;
            float lv = s2 + bl2v;
            float xm = fmaxf(pm, 0.f) + log1pf(expf(-fabsf(pm)));
            float xi = xm + expf(0.5f * lv) * eps[gr];
            xi = fminf(fmaxf(xi, 0.f), 1.f);
            out[gr]            = xm;   // xi_mean
            out[N_ROWS + gr]   = lv;   // xi_lnvar
            g_xi[gr]           = xi;
        }
    }
}

// ---------------------------------------------------------------------------
// Scan kernel: 112 rows/block (448 threads), FOUR threads per row, 16 units
// each packed as 8 f32x2 pairs. Loads clamped / stores guarded for tail block.
// ---------------------------------------------------------------------------
__global__ __launch_bounds__(448, 1)
void scan_kernel(const float* __restrict__ data,
                 const float* __restrict__ omega,
                 const float* __restrict__ Wa1, const float* __restrict__ ba1,
                 const float* __restrict__ Wa2, const float* __restrict__ ba2,
                 float* __restrict__ out)
{
    __shared__ float ytile[BROWS][33];

    const int tid = threadIdx.x;
    const int l4  = tid & 3;
    const int r   = tid >> 2;                 // local row 0..111
    const int row = blockIdx.x * BROWS + r;
    const int rowc = min(row, N_ROWS - 1);

    // this thread's 16 hidden units as 8 pairs: j = l4*16 + 2q
    u64 w2[8], v2[8], c2[8];
    const float om = omega[rowc];
    #pragma unroll
    for (int q = 0; q < 8; q++) {
        int j = l4 * 16 + 2 * q;
        float2 wf = *(const float2*)&Wa1[64 + j];
        float2 vf = *(const float2*)&Wa2[j];
        w2[q] = pack2(wf.x, wf.y);
        v2[q] = pack2(vf.x, vf.y);
        c2[q] = pack2(fmaf(om, Wa1[j],     ba1[j]),
                      fmaf(om, Wa1[j + 1], ba1[j + 1]));
    }
    const float b2v = ba2[0];

    float y  = data[(size_t)rowc * DIM];
    float vv = 0.f;
    const float xi = g_xi[rowc];
    const float dm = expf(-xi * DT_F);
    float f = 1.f;

    float* __restrict__ xout = out + 2 * N_ROWS;

    for (int t = 0; t < 256; t++) {
        if (l4 == 0) ytile[r][t & 31] = f * y;

        u64 y2 = dup2(y);
        u64 acc2a = 0ull, acc2b = 0ull;
        #pragma unroll
        for (int q = 0; q < 8; q += 2) {
            u64 h0, h1;
            FMA2O(h0, y2, w2[q],     c2[q]);
            FMA2O(h1, y2, w2[q + 1], c2[q + 1]);
            FMA2(acc2a, relu2(h0), v2[q]);
            FMA2(acc2b, relu2(h1), v2[q + 1]);
        }
        float alo, ahi, blo, bhi;
        unpk(acc2a, alo, ahi);
        unpk(acc2b, blo, bhi);
        float acc = (alo + ahi) + (blo + bhi);
        acc += __shfl_xor_sync(0xffffffffu, acc, 1);
        acc += __shfl_xor_sync(0xffffffffu, acc, 2);
        acc += b2v;

        float ynew = fmaf(DT_F, vv, y);
        vv = fmaf(DT_F, acc, vv);
        y  = ynew;
        f *= dm;

        if ((t & 31) == 31) {
            __syncthreads();
            int tb = t - 31;
            #pragma unroll
            for (int i = 0; i < 8; i++) {
                int idx = i * 448 + tid;      // 0..3583 over 112x32 tile
                int rr  = idx >> 5;
                int cc  = idx & 31;
                int grow = blockIdx.x * BROWS + rr;
                if (grow < N_ROWS)
                    xout[(size_t)grow * DIM + tb + cc] = ytile[rr][cc];
            }
            __syncthreads();
        }
    }
}

// ---------------------------------------------------------------------------
extern "C" void kernel_launch(void* const* d_in, const int* in_sizes, int n_in,
                              void* d_out, int out_size)
{
    const float* data = (const float*)d_in[0];
    const float* omega= (const float*)d_in[1];
    const float* eps  = (const float*)d_in[2];
    const float* W1   = (const float*)d_in[3];  const float* b1  = (const float*)d_in[4];
    const float* W2   = (const float*)d_in[5];  const float* b2  = (const float*)d_in[6];
    const float* Wm1  = (const float*)d_in[7];  const float* bm1 = (const float*)d_in[8];
    const float* Wm2  = (const float*)d_in[9];  const float* bm2 = (const float*)d_in[10];
    const float* Wl1  = (const float*)d_in[11]; const float* bl1 = (const float*)d_in[12];
    const float* Wl2  = (const float*)d_in[13]; const float* bl2 = (const float*)d_in[14];
    const float* Wa1  = (const float*)d_in[15]; const float* ba1 = (const float*)d_in[16];
    const float* Wa2  = (const float*)d_in[17]; const float* ba2 = (const float*)d_in[18];
    float* out = (float*)d_out;

    cudaFuncSetAttribute(mlp_kernel,
                         cudaFuncAttributeMaxDynamicSharedMemorySize, MLP_SMEM);

    mlp_kernel<<<GRID_N, 256, MLP_SMEM>>>(
        data, omega, eps, W1, b1, W2, b2,
        Wm1, bm1, Wm2, bm2, Wl1, bl1, Wl2, bl2, out);

    scan_kernel<<<GRID_N, 448>>>(data, omega, Wa1, ba1, Wa2, ba2, out);
}